// round 3
// baseline (speedup 1.0000x reference)
#include <cuda_runtime.h>
#include <cuda_bf16.h>

// relu(sum(relu(x))) over N = 2^25 fp32. HBM-bound streaming reduction.
// Fused single kernel, x4-unrolled independent LDG.128 streams (__ldcs),
// 4 accumulators, one full wave (148 SMs x 8 CTAs), last-block tail reduce.

#define NTHREADS 256
#define NBLOCKS (148 * 8)   // 1184 = exactly one full wave at 8 CTAs/SM

__device__ float g_partials[NBLOCKS];
__device__ unsigned int g_count = 0;

__device__ __forceinline__ float relu4(float4 v)
{
    return fmaxf(v.x, 0.0f) + fmaxf(v.y, 0.0f)
         + fmaxf(v.z, 0.0f) + fmaxf(v.w, 0.0f);
}

__device__ __forceinline__ float block_reduce(float acc, float* warp_sums)
{
    #pragma unroll
    for (int off = 16; off > 0; off >>= 1)
        acc += __shfl_xor_sync(0xFFFFFFFFu, acc, off);

    int lane = threadIdx.x & 31;
    int wid = threadIdx.x >> 5;
    if (lane == 0) warp_sums[wid] = acc;
    __syncthreads();

    float s = 0.0f;
    if (wid == 0) {
        s = (lane < NTHREADS / 32) ? warp_sums[lane] : 0.0f;
        #pragma unroll
        for (int off = 16; off > 0; off >>= 1)
            s += __shfl_xor_sync(0xFFFFFFFFu, s, off);
    }
    return s;  // valid in warp 0 lane 0
}

__global__ __launch_bounds__(NTHREADS) void kan_fused_kernel(
    const float* __restrict__ x, int n_vec4, float* __restrict__ out)
{
    const float4* __restrict__ xv = reinterpret_cast<const float4*>(x);
    int tid = blockIdx.x * blockDim.x + threadIdx.x;
    const int stride = NBLOCKS * NTHREADS;

    float a0 = 0.0f, a1 = 0.0f, a2 = 0.0f, a3 = 0.0f;

    int i = tid;
    // 4 independent streaming LDG.128 in flight per iter, 4 accumulators.
    for (; i + 3 * stride < n_vec4; i += 4 * stride) {
        float4 v0 = __ldcs(xv + i);
        float4 v1 = __ldcs(xv + i + stride);
        float4 v2 = __ldcs(xv + i + 2 * stride);
        float4 v3 = __ldcs(xv + i + 3 * stride);
        a0 += relu4(v0);
        a1 += relu4(v1);
        a2 += relu4(v2);
        a3 += relu4(v3);
    }
    for (; i < n_vec4; i += stride)
        a0 += relu4(__ldcs(xv + i));

    float acc = (a0 + a1) + (a2 + a3);

    __shared__ float warp_sums[NTHREADS / 32];
    float bsum = block_reduce(acc, warp_sums);

    // Publish partial, elect last block.
    __shared__ bool is_last;
    if (threadIdx.x == 0) {
        g_partials[blockIdx.x] = bsum;
        __threadfence();
        unsigned int prev = atomicAdd(&g_count, 1u);
        is_last = (prev == (unsigned int)(gridDim.x - 1));
    }
    __syncthreads();

    if (is_last) {
        // 256 threads reduce NBLOCKS partials in fixed order.
        float facc = 0.0f;
        for (int k = threadIdx.x; k < NBLOCKS; k += NTHREADS)
            facc += g_partials[k];

        __syncthreads();  // warp_sums reuse
        float total = block_reduce(facc, warp_sums);

        if (threadIdx.x == 0) {
            out[0] = fmaxf(total, 0.0f);  // outer relu
            g_count = 0;                  // reset for graph replay
        }
    }
}

extern "C" void kernel_launch(void* const* d_in, const int* in_sizes, int n_in,
                              void* d_out, int out_size)
{
    const float* x = (const float*)d_in[0];
    float* out = (float*)d_out;
    int n = in_sizes[0];
    int n_vec4 = n / 4;  // N = 2^25, divisible by 4

    kan_fused_kernel<<<NBLOCKS, NTHREADS>>>(x, n_vec4, out);
}

// round 4
// speedup vs baseline: 1.0736x; 1.0736x over previous
#include <cuda_runtime.h>
#include <cuda_bf16.h>

// relu(sum(relu(x))) over N = 2^25 fp32. HBM-bound streaming reduction.
// Simple unroll-1 grid-stride loop (lowest regs -> 8 CTAs/SM, single full
// wave of 148*8 CTAs), fused last-block-done tail reduce.

#define NTHREADS 256
#define NBLOCKS (148 * 8)   // one full wave at 8 CTAs/SM (64 warps/SM)

__device__ float g_partials[NBLOCKS];
__device__ unsigned int g_count = 0;

__device__ __forceinline__ float relu4(float4 v)
{
    return fmaxf(v.x, 0.0f) + fmaxf(v.y, 0.0f)
         + fmaxf(v.z, 0.0f) + fmaxf(v.w, 0.0f);
}

__device__ __forceinline__ float block_reduce(float acc, float* warp_sums)
{
    #pragma unroll
    for (int off = 16; off > 0; off >>= 1)
        acc += __shfl_xor_sync(0xFFFFFFFFu, acc, off);

    int lane = threadIdx.x & 31;
    int wid = threadIdx.x >> 5;
    if (lane == 0) warp_sums[wid] = acc;
    __syncthreads();

    float s = 0.0f;
    if (wid == 0) {
        s = (lane < NTHREADS / 32) ? warp_sums[lane] : 0.0f;
        #pragma unroll
        for (int off = 16; off > 0; off >>= 1)
            s += __shfl_xor_sync(0xFFFFFFFFu, s, off);
    }
    return s;  // valid in warp 0 lane 0
}

__global__ void __launch_bounds__(NTHREADS, 8) kan_fused_kernel(
    const float* __restrict__ x, int n_vec4, float* __restrict__ out)
{
    const float4* __restrict__ xv = reinterpret_cast<const float4*>(x);
    int tid = blockIdx.x * blockDim.x + threadIdx.x;
    const int stride = NBLOCKS * NTHREADS;

    // Simple grid-stride: one LDG.128 per iter, minimal registers.
    float acc = 0.0f;
    for (int i = tid; i < n_vec4; i += stride)
        acc += relu4(xv[i]);

    __shared__ float warp_sums[NTHREADS / 32];
    float bsum = block_reduce(acc, warp_sums);

    // Publish partial, elect last block.
    __shared__ bool is_last;
    if (threadIdx.x == 0) {
        g_partials[blockIdx.x] = bsum;
        __threadfence();
        unsigned int prev = atomicAdd(&g_count, 1u);
        is_last = (prev == (unsigned int)(gridDim.x - 1));
    }
    __syncthreads();

    if (is_last) {
        // 256 threads reduce NBLOCKS partials in fixed order.
        float facc = 0.0f;
        for (int k = threadIdx.x; k < NBLOCKS; k += NTHREADS)
            facc += g_partials[k];

        __syncthreads();  // warp_sums reuse
        float total = block_reduce(facc, warp_sums);

        if (threadIdx.x == 0) {
            out[0] = fmaxf(total, 0.0f);  // outer relu
            g_count = 0;                  // reset for graph replay
        }
    }
}

extern "C" void kernel_launch(void* const* d_in, const int* in_sizes, int n_in,
                              void* d_out, int out_size)
{
    const float* x = (const float*)d_in[0];
    float* out = (float*)d_out;
    int n = in_sizes[0];
    int n_vec4 = n / 4;  // N = 2^25, divisible by 4

    kan_fused_kernel<<<NBLOCKS, NTHREADS>>>(x, n_vec4, out);
}